// round 14
// baseline (speedup 1.0000x reference)
#include <cuda_runtime.h>

// Bidirectional LSTM, B=16, S=4096, H=F=256.
// 128 persistent CTAs x 384 threads: dir = blockIdx.x>>6, slice = blockIdx.x&63.
// Warps 0-7: h-recurrence (R12-proven pair structure, Wh in registers, gather
// h via ld.cg -> warp-private SMEM -> broadcast LDS dot). Warps 8-11: x-
// projection producers (x via broadcast LDG, Wi from SMEM) filling a 2-slot
// accx ring with produced/consumed smem counters -> x-work leaves the serial
// chain. out-stores moved after the arrival RED (off the release fence).

#define BB 16
#define SS 4096
#define HH 256
#define FF 256
#define G4 1024
#define NSL 64
#define NT 384
#define WSTRIDE 260   // wi_s row stride in floats (16B-aligned, 2-way bank ok)

__device__ float    g_hbuf[2][2][BB * FF];   // [dir][parity t&1][b*F + col]
__device__ unsigned g_cnt[2][32];            // monotonic arrivals (256/step/dir)

__device__ __forceinline__ void fma2(unsigned long long &acc,
                                     unsigned long long a, unsigned long long w) {
    asm("fma.rn.f32x2 %0, %1, %2, %0;" : "+l"(acc) : "l"(a), "l"(w));
}
__device__ __forceinline__ unsigned long long pk2(float lo, float hi) {
    unsigned long long r;
    asm("mov.b64 %0, {%1,%2};" : "=l"(r) : "f"(lo), "f"(hi));
    return r;
}
__device__ __forceinline__ float red2(unsigned long long p) {
    float lo, hi;
    asm("mov.b64 {%0,%1}, %2;" : "=f"(lo), "=f"(hi) : "l"(p));
    return lo + hi;
}
__device__ __forceinline__ float sigm(float x) {
    return 1.0f / (1.0f + __expf(-x));
}
__device__ __forceinline__ float tanh_fast(float x) {
    return 1.0f - 2.0f / (__expf(2.0f * x) + 1.0f);
}

__global__ void lstm_init_kernel() {
    if (threadIdx.x < 2) g_cnt[threadIdx.x][0] = 0u;
}

__global__ void __launch_bounds__(NT, 1) lstm_scan_kernel(
    const float* __restrict__ x,
    const float* __restrict__ Wi_fw, const float* __restrict__ Wh_fw,
    const float* __restrict__ b_fw,
    const float* __restrict__ Wi_rv, const float* __restrict__ Wh_rv,
    const float* __restrict__ b_rv,
    float* __restrict__ out, int write_finals)
{
    extern __shared__ __align__(16) float smem[];
    float* hbw  = smem;                       // 8 warps * 1024 floats (32 KB)
    float* wi_s = hbw + 8 * 1024;             // 16*WSTRIDE floats
    float* ring = wi_s + 16 * WSTRIDE;        // [2][16][16]
    float* zbuf = ring + 2 * 16 * 16;         // [4][4][16]
    __shared__ unsigned prod[4], cons[4];

    const int bx   = blockIdx.x;
    const int dd   = bx >> 6;
    const int sl   = bx & 63;
    const int tid  = threadIdx.x;
    const int w    = tid >> 5;
    const int lane = tid & 31;

    const float* Wi   = dd ? Wi_rv : Wi_fw;
    const float* Wh   = dd ? Wh_rv : Wh_fw;
    const float* bias = dd ? b_rv : b_fw;

    // Stage Wi slice into SMEM (all threads): wi_s[c*WSTRIDE + k]
    for (int idx = tid; idx < 16 * HH; idx += NT) {
        int c = idx >> 8, k = idx & 255;
        int cg = ((c >> 2) << 8) + (sl << 2) + (c & 3);
        wi_s[c * WSTRIDE + k] = Wi[(size_t)k * G4 + cg];
    }
    if (tid < 4) { prod[tid] = 0u; cons[tid] = 0u; }
    __syncthreads();

    if (w < 8) {
        // ================= h-warps (recurrence, critical chain) =============
        const int p    = w >> 1;         // pair: batches 4p..4p+3
        const int half = w & 1;
        const int col8 = lane & 7;
        const int kc   = lane >> 3;      // k-chunk 0..3 (64 k each)
        const int cc   = (half << 3) + col8;
        const int colg = ((cc >> 2) << 8) + (sl << 2) + (cc & 3);

        unsigned long long wh2[32];
#pragma unroll
        for (int j = 0; j < 32; ++j) {
            int k = (kc << 6) + (j << 1);
            wh2[j] = pk2(Wh[(size_t)k * G4 + colg],
                         Wh[(size_t)(k + 1) * G4 + colg]);
        }
        float creg = 0.0f;
        float* hw = hbw + (w << 10);
        float* zb = zbuf + (p << 6);     // [4][16] for this pair
        volatile unsigned* vprod = &prod[p];

        for (int t = 0; t < SS; ++t) {
            if (t > 0) {
                // Wait for all 256 pair-arrivals of step t-1.
                volatile unsigned* gp = &g_cnt[dd][0];
                unsigned tgt = (unsigned)(t << 8);
                if (*gp < tgt) { while (*gp < tgt) __nanosleep(64); }
                __threadfence();
                __syncwarp();
                // Gather h(t-1) rows 4p..4p+3 into warp-private buffer.
                const float* hsrc = &g_hbuf[dd][(t + 1) & 1][0];
#pragma unroll
                for (int r = 0; r < 8; ++r) {
                    int m = (r << 5) + lane;
                    int i = m >> 6, off = m & 63;
                    int src = (((p << 2) + i) << 8) + ((off & 3) << 6) + ((off >> 2) << 2);
                    float4 hv = __ldcg((const float4*)(hsrc + src));
                    *(float4*)(hw + (m << 2)) = hv;
                }
                __syncwarp();
            }
            // accx(t) must be in the ring (x-warps usually far ahead).
            while (*vprod < (unsigned)(t + 1)) { }
            __threadfence_block();
            const float* rg = ring + ((t & 1) << 8);   // [16][16]

#pragma unroll
            for (int i = 0; i < 4; ++i) {
                float s = 0.0f;
                if (t > 0) {
                    const float* vp = hw + (i << 8) + (kc << 2);
                    unsigned long long a0 = 0ull, a1 = 0ull;
#pragma unroll
                    for (int j = 0; j < 16; ++j) {
                        ulonglong2 v = *(const ulonglong2*)(vp + (j << 4));
                        fma2(a0, v.x, wh2[2 * j]);
                        fma2(a1, v.y, wh2[2 * j + 1]);
                    }
                    s = red2(a0) + red2(a1);
                    s += __shfl_xor_sync(0xffffffffu, s, 8);
                    s += __shfl_xor_sync(0xffffffffu, s, 16);
                }
                if (lane < 8)
                    zb[(i << 4) + cc] = rg[(((p << 2) + i) << 4) + cc] + s;
            }
            __syncwarp();
            if (lane == 0) atomicAdd(&cons[p], 1u);   // ring slot consumed

            asm volatile("bar.sync %0, 64;" :: "r"(p + 1) : "memory");

            // Epilogue (even warp lanes 0-15): gates, publish h, release.
            float hn = 0.0f, cn = 0.0f;
            int b2 = 0, col = 0;
            if (half == 0) {
                if (lane < 16) {
                    int b_loc = lane >> 2, hc = lane & 3;
                    b2 = (p << 2) + b_loc;
                    float zi = zb[(b_loc << 4) + 0  + hc];
                    float zf = zb[(b_loc << 4) + 4  + hc];
                    float zg = zb[(b_loc << 4) + 8  + hc];
                    float zo = zb[(b_loc << 4) + 12 + hc];
                    cn = sigm(zf) * creg + sigm(zi) * tanh_fast(zg);
                    hn = sigm(zo) * tanh_fast(cn);
                    creg = cn;
                    col = (sl << 2) + hc;
                    g_hbuf[dd][t & 1][(b2 << 8) + col] = hn;
                    __threadfence();          // h visible at gpu scope
                }
                __syncwarp();                 // lanes' fenced stores -> lane0
                if (lane == 0)
                    atomicAdd(&g_cnt[dd][0], 1u);   // arrival (REDG)
                // out stores AFTER the release (off the critical chain)
                if (lane < 16) {
                    int s_cur = dd ? (SS - 1 - t) : t;
                    out[((size_t)b2 * SS + s_cur) * (2 * FF) + dd * FF + col] = hn;
                    if (t == SS - 1 && write_finals) {
                        size_t base = (size_t)BB * SS * 2 * FF + (size_t)dd * 2 * BB * FF;
                        out[base + b2 * FF + col]           = cn;  // c_final
                        out[base + BB * FF + b2 * FF + col] = hn;  // h_final
                    }
                }
            }
        }
    } else {
        // ================= x-warps (projection producers) ===================
        const int xw   = w - 8;          // batches 4xw..4xw+3
        const int kcH  = lane >> 4;      // 0/1 : k-half of 128
        const int ccx  = lane & 15;
        const int colgx = ((ccx >> 2) << 8) + (sl << 2) + (ccx & 3);
        const float bx = bias[colgx];
        volatile unsigned* vcons = &cons[xw];
        const float* wp0 = wi_s + ccx * WSTRIDE + (kcH << 7);

        for (int t = 0; t < SS; ++t) {
            if (t >= 2) {   // slot reuse: both consumer h-warps done with t-2
                unsigned tgt = (unsigned)(2 * (t - 1));
                while (*vcons < tgt) { }
                __threadfence_block();
            }
            int s_x = dd ? (SS - 1 - t) : t;
            float* rg = ring + ((t & 1) << 8);
#pragma unroll
            for (int i = 0; i < 4; ++i) {
                const ulonglong2* xp = (const ulonglong2*)
                    (x + ((size_t)(4 * xw + i) * SS + s_x) * HH + (kcH << 7));
                const ulonglong2* wp = (const ulonglong2*)wp0;
                unsigned long long a0 = 0ull, a1 = 0ull;
#pragma unroll
                for (int j = 0; j < 32; ++j) {
                    ulonglong2 xv = xp[j];
                    ulonglong2 wv = wp[j];
                    fma2(a0, xv.x, wv.x);
                    fma2(a1, xv.y, wv.y);
                }
                float s = red2(a0) + red2(a1);
                s += __shfl_xor_sync(0xffffffffu, s, 16);
                if (lane < 16)
                    rg[((4 * xw + i) << 4) + ccx] = s + bx;
            }
            __syncwarp();
            if (lane == 0) {
                __threadfence_block();
                atomicAdd(&prod[xw], 1u);    // publish accx(t)
            }
        }
    }
}

extern "C" void kernel_launch(void* const* d_in, const int* in_sizes, int n_in,
                              void* d_out, int out_size) {
    const float* x     = (const float*)d_in[0];
    const float* Wi_fw = (const float*)d_in[1];
    const float* Wh_fw = (const float*)d_in[2];
    const float* b_fw  = (const float*)d_in[3];
    const float* Wi_rv = (const float*)d_in[4];
    const float* Wh_rv = (const float*)d_in[5];
    const float* b_rv  = (const float*)d_in[6];
    float* out = (float*)d_out;

    int write_finals = (out_size >= (int)((size_t)BB * SS * 2 * FF + 4 * BB * FF)) ? 1 : 0;

    size_t smem = (size_t)(8 * 1024 + 16 * WSTRIDE + 2 * 16 * 16 + 4 * 4 * 16)
                  * sizeof(float);
    cudaFuncSetAttribute(lstm_scan_kernel,
                         cudaFuncAttributeMaxDynamicSharedMemorySize, (int)smem);

    lstm_init_kernel<<<1, 32>>>();
    lstm_scan_kernel<<<2 * NSL, NT, smem>>>(x, Wi_fw, Wh_fw, b_fw,
                                            Wi_rv, Wh_rv, b_rv, out, write_finals);
}

// round 15
// speedup vs baseline: 1.4706x; 1.4706x over previous
#include <cuda_runtime.h>

// Bidirectional LSTM, B=16, S=4096, H=F=256.
// 128 persistent CTAs: dir = blockIdx.x>>6, slice = blockIdx.x&63.
// Each CTA owns 4 h-columns -> 16 z-columns. Wh/Wi column slices in REGISTERS
// (packed f32x2). Per step: odd warp of each pair prefetch-stages x(t+1) into a
// pair-shared parity-double-buffered SMEM tile (LDG hides under the poll);
// both warps run ONE fused dot  z = b + x(t)@Wi + h(t-1)@Wh  (single
// accumulator chain); pair bar; even-warp epilogue publishes h, fences,
// syncwarp, lane0 RED arrival; out-stores after the release. Plain volatile
// poll (no nanosleep). Monotonic global counter, 256 arrivals/step/dir.

#define BB 16
#define SS 4096
#define HH 256
#define FF 256
#define G4 1024
#define NSL 64
#define NT 256

__device__ float    g_hbuf[2][2][BB * FF];   // [dir][parity t&1][b*F + col]
__device__ unsigned g_cnt[2][32];            // monotonic arrivals (256/step/dir)

__device__ __forceinline__ void fma2(unsigned long long &acc,
                                     unsigned long long a, unsigned long long w) {
    asm("fma.rn.f32x2 %0, %1, %2, %0;" : "+l"(acc) : "l"(a), "l"(w));
}
__device__ __forceinline__ unsigned long long pk2(float lo, float hi) {
    unsigned long long r;
    asm("mov.b64 %0, {%1,%2};" : "=l"(r) : "f"(lo), "f"(hi));
    return r;
}
__device__ __forceinline__ float red2(unsigned long long p) {
    float lo, hi;
    asm("mov.b64 {%0,%1}, %2;" : "=f"(lo), "=f"(hi) : "l"(p));
    return lo + hi;
}
__device__ __forceinline__ float sigm(float x) {
    return 1.0f / (1.0f + __expf(-x));
}
__device__ __forceinline__ float tanh_fast(float x) {
    return 1.0f - 2.0f / (__expf(2.0f * x) + 1.0f);
}

__global__ void lstm_init_kernel() {
    if (threadIdx.x < 2) g_cnt[threadIdx.x][0] = 0u;
}

__global__ void __launch_bounds__(NT, 1) lstm_scan_kernel(
    const float* __restrict__ x,
    const float* __restrict__ Wi_fw, const float* __restrict__ Wh_fw,
    const float* __restrict__ b_fw,
    const float* __restrict__ Wi_rv, const float* __restrict__ Wh_rv,
    const float* __restrict__ b_rv,
    float* __restrict__ out, int write_finals)
{
    // Interleaved tile layout (per 4-row tile of 256 k):
    //   float offset = i*256 + j*16 + kc*4  holds source k = kc*64 + j*4 .. +3
    //   (chunk m = i*64+off: dst float offset = m*4, src k-offset
    //    ksrc = (off&3)*64 + (off>>2)*4)
    extern __shared__ __align__(16) float smem[];
    float* hbw  = smem;              // 8 warps * 1024 floats (h tiles, private)
    float* xpb  = hbw + 8 * 1024;    // 4 pairs * 2 parities * 1024 (x tiles)
    float* zbuf = xpb + 8 * 1024;    // [4][4][16]

    const int bx   = blockIdx.x;
    const int dd   = bx >> 6;
    const int sl   = bx & 63;
    const int tid  = threadIdx.x;
    const int w    = tid >> 5;
    const int lane = tid & 31;
    const int p    = w >> 1;            // pair: batches 4p..4p+3
    const int half = w & 1;             // which 8 of the 16 z-cols
    const int col8 = lane & 7;
    const int kc   = lane >> 3;         // k-chunk 0..3 (64 k each)
    const int cc   = (half << 3) + col8;            // local z-col 0..15
    const int colg = ((cc >> 2) << 8) + (sl << 2) + (cc & 3);

    const float* Wi = dd ? Wi_rv : Wi_fw;
    const float* Wh = dd ? Wh_rv : Wh_fw;
    const float bcc = (dd ? b_rv : b_fw)[colg];

    // Weight slices in registers, pre-packed for f32x2.
    unsigned long long wh2[32], wi2[32];
#pragma unroll
    for (int j = 0; j < 32; ++j) {
        int k = (kc << 6) + (j << 1);
        wh2[j] = pk2(Wh[(size_t)k * G4 + colg], Wh[(size_t)(k + 1) * G4 + colg]);
        wi2[j] = pk2(Wi[(size_t)k * G4 + colg], Wi[(size_t)(k + 1) * G4 + colg]);
    }

    float creg = 0.0f;                   // c-state (even-warp lanes 0-15)
    float* hw = hbw + (w << 10);         // warp-private h tile
    float* xq = xpb + (p << 11);         // pair x tiles (2 parities)
    float* zb = zbuf + (p << 6);         // pair z tile [4][16]

    // Pre-loop: odd warp stages x(step 0) into parity-0 x tile.
    if (half == 1) {
        int s0 = dd ? (SS - 1) : 0;
#pragma unroll
        for (int r = 0; r < 8; ++r) {
            int m = (r << 5) + lane;
            int i = m >> 6, off = m & 63;
            int ksrc = ((off & 3) << 6) + ((off >> 2) << 2);
            *(float4*)(xq + (m << 2)) =
                *(const float4*)(x + ((size_t)((p << 2) + i) * SS + s0) * HH + ksrc);
        }
    }
    __syncthreads();                     // only CTA-wide sync

    for (int t = 0; t < SS; ++t) {
        // Odd warp: prefetch-stage x(t+1) into the other parity tile.
        // LDG latency hides under the poll/gather below. Readers consume at
        // step t+1, after this step's pair bar -> visibility; previous readers
        // of this parity finished before last step's bar -> no WAR.
        if (half == 1 && t < SS - 1) {
            int sn = dd ? (SS - 2 - t) : (t + 1);
            float* xd = xq + (((t + 1) & 1) << 10);
#pragma unroll
            for (int r = 0; r < 8; ++r) {
                int m = (r << 5) + lane;
                int i = m >> 6, off = m & 63;
                int ksrc = ((off & 3) << 6) + ((off >> 2) << 2);
                *(float4*)(xd + (m << 2)) =
                    *(const float4*)(x + ((size_t)((p << 2) + i) * SS + sn) * HH + ksrc);
            }
        }

        if (t > 0) {
            // Wait for all 256 pair-arrivals of step t-1 (plain volatile spin).
            volatile unsigned* gp = &g_cnt[dd][0];
            unsigned tgt = (unsigned)(t << 8);
            while (*gp < tgt) { }
            __threadfence();                 // acquire before h reads
            __syncwarp();                    // hw WAR vs last step's dot reads

            // Gather h(t-1) rows 4p..4p+3 into warp-private tile.
            const float* hsrc = &g_hbuf[dd][(t + 1) & 1][0];
#pragma unroll
            for (int r = 0; r < 8; ++r) {
                int m = (r << 5) + lane;
                int i = m >> 6, off = m & 63;
                int src = (((p << 2) + i) << 8) + ((off & 3) << 6) + ((off >> 2) << 2);
                float4 hv = __ldcg((const float4*)(hsrc + src));
                *(float4*)(hw + (m << 2)) = hv;
            }
            __syncwarp();
        }

        // Fused dot: z = bcc + x(t)@Wi + h(t-1)@Wh  (one accumulator chain).
        const float* xv = xq + ((t & 1) << 10);
#pragma unroll
        for (int i = 0; i < 4; ++i) {
            unsigned long long a0 = 0ull, a1 = 0ull;
            const float* vx = xv + (i << 8) + (kc << 2);
#pragma unroll
            for (int j = 0; j < 16; ++j) {
                ulonglong2 v = *(const ulonglong2*)(vx + (j << 4));
                fma2(a0, v.x, wi2[2 * j]);
                fma2(a1, v.y, wi2[2 * j + 1]);
            }
            if (t > 0) {
                const float* vh = hw + (i << 8) + (kc << 2);
#pragma unroll
                for (int j = 0; j < 16; ++j) {
                    ulonglong2 v = *(const ulonglong2*)(vh + (j << 4));
                    fma2(a0, v.x, wh2[2 * j]);
                    fma2(a1, v.y, wh2[2 * j + 1]);
                }
            }
            float s = red2(a0) + red2(a1);
            s += __shfl_xor_sync(0xffffffffu, s, 8);
            s += __shfl_xor_sync(0xffffffffu, s, 16);
            if (lane < 8) zb[(i << 4) + cc] = bcc + s;
        }

        // Pair barrier: zbuf complete (and stage-x of t ordered for t+1).
        asm volatile("bar.sync %0, 64;" :: "r"(p + 1) : "memory");

        // Epilogue (even warp): gates, publish h, sound release, then out.
        if (half == 0) {
            float hn = 0.0f, cn = 0.0f;
            int b2 = 0, col = 0;
            if (lane < 16) {
                int b_loc = lane >> 2, hc = lane & 3;
                b2 = (p << 2) + b_loc;
                float zi = zb[(b_loc << 4) + 0  + hc];
                float zf = zb[(b_loc << 4) + 4  + hc];
                float zg = zb[(b_loc << 4) + 8  + hc];
                float zo = zb[(b_loc << 4) + 12 + hc];
                cn = sigm(zf) * creg + sigm(zi) * tanh_fast(zg);
                hn = sigm(zo) * tanh_fast(cn);
                creg = cn;
                col = (sl << 2) + hc;
                g_hbuf[dd][t & 1][(b2 << 8) + col] = hn;
                __threadfence();             // own h-store visible at gpu scope
            }
            __syncwarp();                    // lanes' fenced stores -> lane0
            if (lane == 0)
                atomicAdd(&g_cnt[dd][0], 1u);   // arrival (REDG)
            // out-stores AFTER the release (off the critical chain)
            if (lane < 16) {
                int s_cur = dd ? (SS - 1 - t) : t;
                out[((size_t)b2 * SS + s_cur) * (2 * FF) + dd * FF + col] = hn;
                if (t == SS - 1 && write_finals) {
                    size_t base = (size_t)BB * SS * 2 * FF + (size_t)dd * 2 * BB * FF;
                    out[base + b2 * FF + col]           = cn;  // c_final
                    out[base + BB * FF + b2 * FF + col] = hn;  // h_final
                }
            }
        }
    }
}

extern "C" void kernel_launch(void* const* d_in, const int* in_sizes, int n_in,
                              void* d_out, int out_size) {
    const float* x     = (const float*)d_in[0];
    const float* Wi_fw = (const float*)d_in[1];
    const float* Wh_fw = (const float*)d_in[2];
    const float* b_fw  = (const float*)d_in[3];
    const float* Wi_rv = (const float*)d_in[4];
    const float* Wh_rv = (const float*)d_in[5];
    const float* b_rv  = (const float*)d_in[6];
    float* out = (float*)d_out;

    int write_finals = (out_size >= (int)((size_t)BB * SS * 2 * FF + 4 * BB * FF)) ? 1 : 0;

    size_t smem = (size_t)(8 * 1024 + 8 * 1024 + 4 * 4 * 16) * sizeof(float);
    cudaFuncSetAttribute(lstm_scan_kernel,
                         cudaFuncAttributeMaxDynamicSharedMemorySize, (int)smem);

    lstm_init_kernel<<<1, 32>>>();
    lstm_scan_kernel<<<2 * NSL, NT, smem>>>(x, Wi_fw, Wh_fw, b_fw,
                                            Wi_rv, Wh_rv, b_rv, out, write_finals);
}

// round 16
// speedup vs baseline: 2.0201x; 1.3736x over previous
#include <cuda_runtime.h>

// Bidirectional LSTM, B=16, S=4096, H=F=256.
// 128 persistent CTAs: dir = blockIdx.x>>6, slice = blockIdx.x&63.
// Each CTA owns 4 h-columns -> 16 z-columns. Wh/Wi column slices in REGISTERS
// (packed f32x2). R12 skeleton with redundancy removed from the serial path:
//  - pair-SHARED h tile, gather split half/half across the pair's two warps
//  - x(t+1) staged by the odd warp only (overlaps even warp's epilogue) into a
//    pair-shared tile; x-dot stays post-arrival/pre-poll (skew-absorbing)
//  - out-stores moved after the arrival RED (release fence drains h only)
// Sync: monotonic global counter, 256 pair-arrivals/step/dir, nanosleep poll,
// publish->fence->syncwarp->lane0 RED (R12-proven).

#define BB 16
#define SS 4096
#define HH 256
#define FF 256
#define G4 1024
#define NSL 64
#define NT 256

__device__ float    g_hbuf[2][2][BB * FF];   // [dir][parity t&1][b*F + col]
__device__ unsigned g_cnt[2][32];            // monotonic arrivals (256/step/dir)

__device__ __forceinline__ void fma2(unsigned long long &acc,
                                     unsigned long long a, unsigned long long w) {
    asm("fma.rn.f32x2 %0, %1, %2, %0;" : "+l"(acc) : "l"(a), "l"(w));
}
__device__ __forceinline__ unsigned long long pk2(float lo, float hi) {
    unsigned long long r;
    asm("mov.b64 %0, {%1,%2};" : "=l"(r) : "f"(lo), "f"(hi));
    return r;
}
__device__ __forceinline__ float red2(unsigned long long p) {
    float lo, hi;
    asm("mov.b64 {%0,%1}, %2;" : "=f"(lo), "=f"(hi) : "l"(p));
    return lo + hi;
}
__device__ __forceinline__ float sigm(float x) {
    return 1.0f / (1.0f + __expf(-x));
}
__device__ __forceinline__ float tanh_fast(float x) {
    return 1.0f - 2.0f / (__expf(2.0f * x) + 1.0f);
}

__global__ void lstm_init_kernel() {
    if (threadIdx.x < 2) g_cnt[threadIdx.x][0] = 0u;
}

__global__ void __launch_bounds__(NT, 1) lstm_scan_kernel(
    const float* __restrict__ x,
    const float* __restrict__ Wi_fw, const float* __restrict__ Wh_fw,
    const float* __restrict__ b_fw,
    const float* __restrict__ Wi_rv, const float* __restrict__ Wh_rv,
    const float* __restrict__ b_rv,
    float* __restrict__ out, int write_finals)
{
    // Interleaved tile layout (per 4-row tile of 256 k):
    //   chunk m = i*64 + off  (i=row, off=0..63): dst float offset = m*4,
    //   src k-offset ksrc = (off&3)*64 + (off>>2)*4
    //   dot reads row i at (i<<8)+(kc<<2), 16 chunks of 16B, 8-way broadcast.
    __shared__ __align__(16) float hpt[4][4 * HH];   // pair-shared h tiles, 16KB
    __shared__ __align__(16) float xpt[4][4 * HH];   // pair-shared x tiles, 16KB
    __shared__ float zbuf[4][4][16];                 // [pair][batch][z-col]

    const int bx   = blockIdx.x;
    const int dd   = bx >> 6;
    const int sl   = bx & 63;
    const int tid  = threadIdx.x;
    const int w    = tid >> 5;
    const int lane = tid & 31;
    const int p    = w >> 1;            // pair: batches 4p..4p+3
    const int half = w & 1;             // which 8 of the 16 z-cols
    const int col8 = lane & 7;
    const int kc   = lane >> 3;         // k-chunk 0..3 (64 k each)
    const int cc   = (half << 3) + col8;            // local z-col 0..15
    const int colg = ((cc >> 2) << 8) + (sl << 2) + (cc & 3);

    const float* Wi = dd ? Wi_rv : Wi_fw;
    const float* Wh = dd ? Wh_rv : Wh_fw;
    const float bcc = (dd ? b_rv : b_fw)[colg];

    // Weight slices in registers, pre-packed for f32x2.
    unsigned long long wh2[32], wi2[32];
#pragma unroll
    for (int j = 0; j < 32; ++j) {
        int k = (kc << 6) + (j << 1);
        wh2[j] = pk2(Wh[(size_t)k * G4 + colg], Wh[(size_t)(k + 1) * G4 + colg]);
        wi2[j] = pk2(Wi[(size_t)k * G4 + colg], Wi[(size_t)(k + 1) * G4 + colg]);
    }

    float creg = 0.0f;                   // c-state (even-warp lanes 0-15)
    float* hp = &hpt[p][0];
    float* xp = &xpt[p][0];
    float* zb = &zbuf[p][0][0];

    // Pre-loop: odd warp stages x(step 0); CTA sync; both warps x-project.
    if (half == 1) {
        int s0 = dd ? (SS - 1) : 0;
#pragma unroll
        for (int r = 0; r < 8; ++r) {
            int m = (r << 5) + lane;
            int i = m >> 6, off = m & 63;
            int ksrc = ((off & 3) << 6) + ((off >> 2) << 2);
            *(float4*)(xp + (m << 2)) =
                *(const float4*)(x + ((size_t)((p << 2) + i) * SS + s0) * HH + ksrc);
        }
    }
    __syncthreads();

    float accx[4];
#pragma unroll
    for (int i = 0; i < 4; ++i) {
        const float* vx = xp + (i << 8) + (kc << 2);
        unsigned long long a0 = 0ull, a1 = 0ull;
#pragma unroll
        for (int j = 0; j < 16; ++j) {
            ulonglong2 v = *(const ulonglong2*)(vx + (j << 4));
            fma2(a0, v.x, wi2[2 * j]);
            fma2(a1, v.y, wi2[2 * j + 1]);
        }
        float s = red2(a0) + red2(a1);
        s += __shfl_xor_sync(0xffffffffu, s, 8);
        s += __shfl_xor_sync(0xffffffffu, s, 16);
        accx[i] = bcc + s;
    }

    for (int t = 0; t < SS; ++t) {
        if (t > 0) {
            // Wait for all 256 pair-arrivals of step t-1 (monotonic counter).
            volatile unsigned* gp = &g_cnt[dd][0];
            unsigned tgt = (unsigned)(t << 8);
            if (*gp < tgt) {
                while (*gp < tgt) __nanosleep(64);
            }
            __threadfence();                 // acquire before h reads

            // Gather h(t-1): SPLIT across the pair. Each warp loads 2 rows
            // (4 chunks/lane) into the pair-shared tile.
            const float* hsrc = &g_hbuf[dd][(t + 1) & 1][0];
#pragma unroll
            for (int r = 0; r < 4; ++r) {
                int m = (half << 7) + (r << 5) + lane;
                int i = m >> 6, off = m & 63;
                int src = (((p << 2) + i) << 8) + ((off & 3) << 6) + ((off >> 2) << 2);
                float4 hv = __ldcg((const float4*)(hsrc + src));
                *(float4*)(hp + (m << 2)) = hv;
            }
            // Pair barrier: both halves of the tile in place (drains STS).
            asm volatile("bar.sync %0, 64;" :: "r"(p + 1) : "memory");

            // h-dot: z = accx + h(t-1) @ Wh[:, colg]
#pragma unroll
            for (int i = 0; i < 4; ++i) {
                const float* vh = hp + (i << 8) + (kc << 2);
                unsigned long long a0 = 0ull, a1 = 0ull;
#pragma unroll
                for (int j = 0; j < 16; ++j) {
                    ulonglong2 v = *(const ulonglong2*)(vh + (j << 4));
                    fma2(a0, v.x, wh2[2 * j]);
                    fma2(a1, v.y, wh2[2 * j + 1]);
                }
                float s = red2(a0) + red2(a1);
                s += __shfl_xor_sync(0xffffffffu, s, 8);
                s += __shfl_xor_sync(0xffffffffu, s, 16);
                if (lane < 8) zb[(i << 4) + cc] = accx[i] + s;
            }
        } else {
#pragma unroll
            for (int i = 0; i < 4; ++i)
                if (lane < 8) zb[(i << 4) + cc] = accx[i];   // h(-1) = 0
        }

        // Pair barrier: zbuf complete (also orders last step's tile reads
        // before this step's odd-warp x-stage overwrite below).
        asm volatile("bar.sync %0, 64;" :: "r"(p + 1) : "memory");

        // Even warp: epilogue (gates, publish h, sound release, then outs).
        // Odd warp (concurrently): stage x(t+1) into the pair-shared tile.
        if (half == 0) {
            float hn = 0.0f, cn = 0.0f;
            int b2 = 0, col = 0;
            if (lane < 16) {
                int b_loc = lane >> 2, hc = lane & 3;
                b2 = (p << 2) + b_loc;
                float zi = zb[(b_loc << 4) + 0  + hc];
                float zf = zb[(b_loc << 4) + 4  + hc];
                float zg = zb[(b_loc << 4) + 8  + hc];
                float zo = zb[(b_loc << 4) + 12 + hc];
                cn = sigm(zf) * creg + sigm(zi) * tanh_fast(zg);
                hn = sigm(zo) * tanh_fast(cn);
                creg = cn;
                col = (sl << 2) + hc;
                g_hbuf[dd][t & 1][(b2 << 8) + col] = hn;
                __threadfence();             // own h-store visible at gpu scope
            }
            __syncwarp();                    // lanes' fenced stores -> lane0
            if (lane == 0)
                atomicAdd(&g_cnt[dd][0], 1u);   // arrival (REDG)
            // out-stores AFTER the release (off the critical chain)
            if (lane < 16) {
                int s_cur = dd ? (SS - 1 - t) : t;
                out[((size_t)b2 * SS + s_cur) * (2 * FF) + dd * FF + col] = hn;
                if (t == SS - 1 && write_finals) {
                    size_t base = (size_t)BB * SS * 2 * FF + (size_t)dd * 2 * BB * FF;
                    out[base + b2 * FF + col]           = cn;  // c_final
                    out[base + BB * FF + b2 * FF + col] = hn;  // h_final
                }
            }
        } else if (t < SS - 1) {
            int sn = dd ? (SS - 2 - t) : (t + 1);
#pragma unroll
            for (int r = 0; r < 8; ++r) {
                int m = (r << 5) + lane;
                int i = m >> 6, off = m & 63;
                int ksrc = ((off & 3) << 6) + ((off >> 2) << 2);
                *(float4*)(xp + (m << 2)) =
                    *(const float4*)(x + ((size_t)((p << 2) + i) * SS + sn) * HH + ksrc);
            }
        }
        if (t == SS - 1) break;

        // Pair barrier: x tile staged; then x-dot (post-arrival, pre-poll —
        // this segment absorbs inter-CTA skew).
        asm volatile("bar.sync %0, 64;" :: "r"(p + 1) : "memory");
#pragma unroll
        for (int i = 0; i < 4; ++i) {
            const float* vx = xp + (i << 8) + (kc << 2);
            unsigned long long a0 = 0ull, a1 = 0ull;
#pragma unroll
            for (int j = 0; j < 16; ++j) {
                ulonglong2 v = *(const ulonglong2*)(vx + (j << 4));
                fma2(a0, v.x, wi2[2 * j]);
                fma2(a1, v.y, wi2[2 * j + 1]);
            }
            float s = red2(a0) + red2(a1);
            s += __shfl_xor_sync(0xffffffffu, s, 8);
            s += __shfl_xor_sync(0xffffffffu, s, 16);
            accx[i] = bcc + s;
        }
    }
}

extern "C" void kernel_launch(void* const* d_in, const int* in_sizes, int n_in,
                              void* d_out, int out_size) {
    const float* x     = (const float*)d_in[0];
    const float* Wi_fw = (const float*)d_in[1];
    const float* Wh_fw = (const float*)d_in[2];
    const float* b_fw  = (const float*)d_in[3];
    const float* Wi_rv = (const float*)d_in[4];
    const float* Wh_rv = (const float*)d_in[5];
    const float* b_rv  = (const float*)d_in[6];
    float* out = (float*)d_out;

    int write_finals = (out_size >= (int)((size_t)BB * SS * 2 * FF + 4 * BB * FF)) ? 1 : 0;

    lstm_init_kernel<<<1, 32>>>();
    lstm_scan_kernel<<<2 * NSL, NT>>>(x, Wi_fw, Wh_fw, b_fw,
                                      Wi_rv, Wh_rv, b_rv, out, write_finals);
}

// round 17
// speedup vs baseline: 2.0251x; 1.0025x over previous
#include <cuda_runtime.h>

// Bidirectional LSTM, B=16, S=4096, H=F=256.
// 128 persistent CTAs: dir = blockIdx.x>>6, slice = blockIdx.x&63.
// R15 skeleton (pair-shared tiles, register weights, split gather, pair bars,
// publish->fence->syncwarp->lane0 RED) with:
//  1. designated-poller sync: warp0 tight-spins the global counter (64 CTAs/
//     word, no L2 slice congestion, no nanosleep jitter), gpu acquire fence,
//     then __syncthreads broadcast (coop-groups grid-sync pattern).
//  2. x(t+1) staged at TOP of step into parity-double-buffered pair tile
//     (LDG hides under the wait); 3rd pair-bar deleted; x-dot stays at end.
//  3. h/out/finals publish vectorized to STG.128 via lane shuffles (4 stores,
//     not 16 -> cheaper release fence).

#define BB 16
#define SS 4096
#define HH 256
#define FF 256
#define G4 1024
#define NSL 64
#define NT 256

__device__ float    g_hbuf[2][2][BB * FF];   // [dir][parity t&1][b*F + col]
__device__ unsigned g_cnt[2][32];            // monotonic arrivals (256/step/dir)

__device__ __forceinline__ void fma2(unsigned long long &acc,
                                     unsigned long long a, unsigned long long w) {
    asm("fma.rn.f32x2 %0, %1, %2, %0;" : "+l"(acc) : "l"(a), "l"(w));
}
__device__ __forceinline__ unsigned long long pk2(float lo, float hi) {
    unsigned long long r;
    asm("mov.b64 %0, {%1,%2};" : "=l"(r) : "f"(lo), "f"(hi));
    return r;
}
__device__ __forceinline__ float red2(unsigned long long p) {
    float lo, hi;
    asm("mov.b64 {%0,%1}, %2;" : "=f"(lo), "=f"(hi) : "l"(p));
    return lo + hi;
}
__device__ __forceinline__ float sigm(float x) {
    return 1.0f / (1.0f + __expf(-x));
}
__device__ __forceinline__ float tanh_fast(float x) {
    return 1.0f - 2.0f / (__expf(2.0f * x) + 1.0f);
}

__global__ void lstm_init_kernel() {
    if (threadIdx.x < 2) g_cnt[threadIdx.x][0] = 0u;
}

__global__ void __launch_bounds__(NT, 1) lstm_scan_kernel(
    const float* __restrict__ x,
    const float* __restrict__ Wi_fw, const float* __restrict__ Wh_fw,
    const float* __restrict__ b_fw,
    const float* __restrict__ Wi_rv, const float* __restrict__ Wh_rv,
    const float* __restrict__ b_rv,
    float* __restrict__ out, int write_finals)
{
    // Interleaved tile layout (per 4-row tile of 256 k):
    //   chunk m = i*64 + off: dst float offset = m*4,
    //   src k-offset ksrc = (off&3)*64 + (off>>2)*4
    //   dot reads row i at (i<<8)+(kc<<2): 16 chunks of 16B, 8-way broadcast.
    extern __shared__ __align__(16) float smem[];
    float* hpt  = smem;                 // 4 pairs * 1024  (h tiles)      16KB
    float* xpt  = hpt + 4 * 1024;       // 4 pairs * 2 * 1024 (x parity)  32KB
    float* zbuf = xpt + 8 * 1024;       // [4][4][16]                      1KB

    const int bx   = blockIdx.x;
    const int dd   = bx >> 6;
    const int sl   = bx & 63;
    const int tid  = threadIdx.x;
    const int w    = tid >> 5;
    const int lane = tid & 31;
    const int p    = w >> 1;            // pair: batches 4p..4p+3
    const int half = w & 1;             // which 8 of the 16 z-cols
    const int col8 = lane & 7;
    const int kc   = lane >> 3;         // k-chunk 0..3 (64 k each)
    const int cc   = (half << 3) + col8;            // local z-col 0..15
    const int colg = ((cc >> 2) << 8) + (sl << 2) + (cc & 3);

    const float* Wi = dd ? Wi_rv : Wi_fw;
    const float* Wh = dd ? Wh_rv : Wh_fw;
    const float bcc = (dd ? b_rv : b_fw)[colg];

    // Weight slices in registers, pre-packed for f32x2.
    unsigned long long wh2[32], wi2[32];
#pragma unroll
    for (int j = 0; j < 32; ++j) {
        int k = (kc << 6) + (j << 1);
        wh2[j] = pk2(Wh[(size_t)k * G4 + colg], Wh[(size_t)(k + 1) * G4 + colg]);
        wi2[j] = pk2(Wi[(size_t)k * G4 + colg], Wi[(size_t)(k + 1) * G4 + colg]);
    }

    float creg = 0.0f;                   // c-state (even-warp lanes 0-15)
    float* hp = hpt + (p << 10);
    float* xq = xpt + (p << 11);         // 2 parity tiles of 1024 floats
    float* zb = zbuf + (p << 6);

    // Pre-loop: odd warp stages x(0) into parity 0; CTA sync; x-project.
    if (half == 1) {
        int s0 = dd ? (SS - 1) : 0;
#pragma unroll
        for (int r = 0; r < 8; ++r) {
            int m = (r << 5) + lane;
            int i = m >> 6, off = m & 63;
            int ksrc = ((off & 3) << 6) + ((off >> 2) << 2);
            *(float4*)(xq + (m << 2)) =
                *(const float4*)(x + ((size_t)((p << 2) + i) * SS + s0) * HH + ksrc);
        }
    }
    __syncthreads();

    float accx[4];
#pragma unroll
    for (int i = 0; i < 4; ++i) {
        const float* vx = xq + (i << 8) + (kc << 2);
        unsigned long long a0 = 0ull, a1 = 0ull;
#pragma unroll
        for (int j = 0; j < 16; ++j) {
            ulonglong2 v = *(const ulonglong2*)(vx + (j << 4));
            fma2(a0, v.x, wi2[2 * j]);
            fma2(a1, v.y, wi2[2 * j + 1]);
        }
        float s = red2(a0) + red2(a1);
        s += __shfl_xor_sync(0xffffffffu, s, 8);
        s += __shfl_xor_sync(0xffffffffu, s, 16);
        accx[i] = bcc + s;
    }

    for (int t = 0; t < SS; ++t) {
        // Top-of-step: odd warp stages x(t+1) into the other parity tile.
        // LDG latency hides under the poll/syncthreads wait below.
        if (half == 1 && t < SS - 1) {
            int sn = dd ? (SS - 2 - t) : (t + 1);
            float* xd = xq + (((t + 1) & 1) << 10);
#pragma unroll
            for (int r = 0; r < 8; ++r) {
                int m = (r << 5) + lane;
                int i = m >> 6, off = m & 63;
                int ksrc = ((off & 3) << 6) + ((off >> 2) << 2);
                *(float4*)(xd + (m << 2)) =
                    *(const float4*)(x + ((size_t)((p << 2) + i) * SS + sn) * HH + ksrc);
            }
        }

        if (t > 0) {
            // Designated poller: warp 0 tight-spins the global counter,
            // acquire-fences, then releases the CTA barrier.
            if (w == 0) {
                volatile unsigned* gp = &g_cnt[dd][0];
                unsigned tgt = (unsigned)(t << 8);
                while (*gp < tgt) { }
                __threadfence();             // gpu-scope acquire
            }
            __syncthreads();                 // broadcast + memory ordering

            // Gather h(t-1): split half/half across the pair's two warps.
            const float* hsrc = &g_hbuf[dd][(t + 1) & 1][0];
#pragma unroll
            for (int r = 0; r < 4; ++r) {
                int m = (half << 7) + (r << 5) + lane;
                int i = m >> 6, off = m & 63;
                int src = (((p << 2) + i) << 8) + ((off & 3) << 6) + ((off >> 2) << 2);
                float4 hv = __ldcg((const float4*)(hsrc + src));
                *(float4*)(hp + (m << 2)) = hv;
            }
            asm volatile("bar.sync %0, 64;" :: "r"(p + 1) : "memory");

            // h-dot: z = accx + h(t-1) @ Wh[:, colg]
#pragma unroll
            for (int i = 0; i < 4; ++i) {
                const float* vh = hp + (i << 8) + (kc << 2);
                unsigned long long a0 = 0ull, a1 = 0ull;
#pragma unroll
                for (int j = 0; j < 16; ++j) {
                    ulonglong2 v = *(const ulonglong2*)(vh + (j << 4));
                    fma2(a0, v.x, wh2[2 * j]);
                    fma2(a1, v.y, wh2[2 * j + 1]);
                }
                float s = red2(a0) + red2(a1);
                s += __shfl_xor_sync(0xffffffffu, s, 8);
                s += __shfl_xor_sync(0xffffffffu, s, 16);
                if (lane < 8) zb[(i << 4) + cc] = accx[i] + s;
            }
        } else {
#pragma unroll
            for (int i = 0; i < 4; ++i)
                if (lane < 8) zb[(i << 4) + cc] = accx[i];   // h(-1) = 0
        }

        // Pair barrier: zbuf complete; also orders x-stage (top) for the
        // x-dot at the end of this step, and epilogue's zb reads.
        asm volatile("bar.sync %0, 64;" :: "r"(p + 1) : "memory");

        // Even warp: epilogue. Gates, vectorized publish, sound release, outs.
        if (half == 0) {
            float hn = 0.0f, cn = 0.0f;
            int b2 = (p << 2) + (lane >> 2);
            if (lane < 16) {
                int b_loc = lane >> 2, hc = lane & 3;
                float zi = zb[(b_loc << 4) + 0  + hc];
                float zf = zb[(b_loc << 4) + 4  + hc];
                float zg = zb[(b_loc << 4) + 8  + hc];
                float zo = zb[(b_loc << 4) + 12 + hc];
                cn = sigm(zf) * creg + sigm(zi) * tanh_fast(zg);
                hn = sigm(zo) * tanh_fast(cn);
                creg = cn;
            }
            // Assemble float4 per batch in lanes 0,4,8,12 via shuffles.
            float h1 = __shfl_down_sync(0xffffffffu, hn, 1);
            float h2 = __shfl_down_sync(0xffffffffu, hn, 2);
            float h3 = __shfl_down_sync(0xffffffffu, hn, 3);
            float4 hv4 = make_float4(hn, h1, h2, h3);
            bool pub = (lane < 16) && ((lane & 3) == 0);
            if (pub) {
                *(float4*)&g_hbuf[dd][t & 1][(b2 << 8) + (sl << 2)] = hv4;
                __threadfence();             // publisher's store -> gpu scope
            }
            __syncwarp();                    // publishers' fences -> lane0
            if (lane == 0)
                atomicAdd(&g_cnt[dd][0], 1u);   // arrival (REDG)
            // out/finals AFTER the release (off the critical chain)
            if (pub) {
                int s_cur = dd ? (SS - 1 - t) : t;
                *(float4*)&out[((size_t)b2 * SS + s_cur) * (2 * FF)
                               + dd * FF + (sl << 2)] = hv4;
            }
            if (t == SS - 1 && write_finals) {
                float c1 = __shfl_down_sync(0xffffffffu, cn, 1);
                float c2 = __shfl_down_sync(0xffffffffu, cn, 2);
                float c3 = __shfl_down_sync(0xffffffffu, cn, 3);
                if (pub) {
                    float4 cv4 = make_float4(cn, c1, c2, c3);
                    size_t base = (size_t)BB * SS * 2 * FF + (size_t)dd * 2 * BB * FF;
                    *(float4*)&out[base + b2 * FF + (sl << 2)]           = cv4;
                    *(float4*)&out[base + BB * FF + b2 * FF + (sl << 2)] = hv4;
                }
            }
        }
        if (t == SS - 1) break;

        // End-of-step x-dot: accx(t+1) from parity (t+1)&1 (staged at top,
        // ordered by the bars). Post-arrival, pre-poll: absorbs CTA skew.
        const float* xv = xq + (((t + 1) & 1) << 10);
#pragma unroll
        for (int i = 0; i < 4; ++i) {
            const float* vx = xv + (i << 8) + (kc << 2);
            unsigned long long a0 = 0ull, a1 = 0ull;
#pragma unroll
            for (int j = 0; j < 16; ++j) {
                ulonglong2 v = *(const ulonglong2*)(vx + (j << 4));
                fma2(a0, v.x, wi2[2 * j]);
                fma2(a1, v.y, wi2[2 * j + 1]);
            }
            float s = red2(a0) + red2(a1);
            s += __shfl_xor_sync(0xffffffffu, s, 8);
            s += __shfl_xor_sync(0xffffffffu, s, 16);
            accx[i] = bcc + s;
        }
    }
}

extern "C" void kernel_launch(void* const* d_in, const int* in_sizes, int n_in,
                              void* d_out, int out_size) {
    const float* x     = (const float*)d_in[0];
    const float* Wi_fw = (const float*)d_in[1];
    const float* Wh_fw = (const float*)d_in[2];
    const float* b_fw  = (const float*)d_in[3];
    const float* Wi_rv = (const float*)d_in[4];
    const float* Wh_rv = (const float*)d_in[5];
    const float* b_rv  = (const float*)d_in[6];
    float* out = (float*)d_out;

    int write_finals = (out_size >= (int)((size_t)BB * SS * 2 * FF + 4 * BB * FF)) ? 1 : 0;

    size_t smem = (size_t)(4 * 1024 + 8 * 1024 + 4 * 4 * 16) * sizeof(float);
    cudaFuncSetAttribute(lstm_scan_kernel,
                         cudaFuncAttributeMaxDynamicSharedMemorySize, (int)smem);

    lstm_init_kernel<<<1, 32>>>();
    lstm_scan_kernel<<<2 * NSL, NT, smem>>>(x, Wi_fw, Wh_fw, b_fw,
                                            Wi_rv, Wh_rv, b_rv, out, write_finals);
}